// round 2
// baseline (speedup 1.0000x reference)
#include <cuda_runtime.h>

// ---------------------------------------------------------------------------
// CharacterEmbeddingLayer: char-CNN (windows 2..5, 100 filters each, tanh +
// maxpool) -> 400 feats -> 400x128 projection -> 2 highway layers -> [.,128].
// ---------------------------------------------------------------------------

#define NTOK  25600      // 64*400 tokens
#define NF    100

typedef unsigned long long u64;

// scratch for conv outputs: [NTOK, 400] fp32
__device__ float g_outs[(size_t)NTOK * 400];

// ---------------- packed fp32x2 helpers (sm_100+) ---------------------------
__device__ __forceinline__ void ffma2(u64 &acc, u64 a, u64 b) {
    asm("fma.rn.f32x2 %0, %1, %2, %0;" : "+l"(acc) : "l"(a), "l"(b));
}
__device__ __forceinline__ u64 pack2(float lo, float hi) {
    u64 r; asm("mov.b64 %0, {%1, %2};" : "=l"(r) : "f"(lo), "f"(hi)); return r;
}
__device__ __forceinline__ float hadd2(u64 v) {
    float lo, hi;
    asm("mov.b64 {%0, %1}, %2;" : "=f"(lo), "=f"(hi) : "l"(v));
    return lo + hi;
}
__device__ __forceinline__ float tanh_fast(float x) {
    float y;
    asm("tanh.approx.f32 %0, %1;" : "=f"(y) : "f"(x));
    return y;
}

// ---------------------------------------------------------------------------
// Kernel 1: conv branches. 8 tokens/CTA (1 token per warp), 256 threads.
// Embeds come straight from char_vectors (24KB, L1-resident) via broadcast
// __ldg through 16 per-token row pointers kept in registers -> no embed smem,
// no crossbar cost. Filters staged in smem, lane = filter (3 tiles of 32),
// last 4 filters done as (filter,position)-split across lanes (no waste).
// ---------------------------------------------------------------------------
#define TPC      8
#define T1       256
#define PITCH    324                      // floats; odd quad stride -> no conflicts
#define SMEM1_BYTES (32 * PITCH * 4)      // 41472 B

template<int W>
__device__ __forceinline__ float conv_dot(const float4* const (&ep)[16],
                                          const float* __restrict__ frow)
{
    constexpr int L = 17 - W;             // valid window positions
    u64 acc[L];
    #pragma unroll
    for (int l = 0; l < L; l++) acc[l] = 0ull;

    #pragma unroll 2
    for (int d4 = 0; d4 < 16; d4++) {     // 4 fp32 of the d-dim per step
        ulonglong2 fv[W];
        #pragma unroll
        for (int p = 0; p < W; p++)
            fv[p] = *reinterpret_cast<const ulonglong2*>(frow + p * 64 + 4 * d4);
        #pragma unroll
        for (int j = 0; j < 16; j++) {
            const float4 e = __ldg(ep[j] + d4);    // warp-broadcast, L1 hit
            const u64 ex = pack2(e.x, e.y);
            const u64 ey = pack2(e.z, e.w);
            #pragma unroll
            for (int p = 0; p < W; p++) {
                const int l = j - p;               // folded at compile time
                if (l >= 0 && l < L) {
                    ffma2(acc[l], ex, fv[p].x);
                    ffma2(acc[l], ey, fv[p].y);
                }
            }
        }
    }
    float vm = -2.0f;                               // tanh in [-1,1]
    #pragma unroll
    for (int l = 0; l < L; l++)
        vm = fmaxf(vm, tanh_fast(hadd2(acc[l])));
    return vm;
}

template<int W>
__device__ __forceinline__ void stage_filters(const float* __restrict__ filt,
                                              float* fs, int f0, int tid)
{
    constexpr int KW4 = W * 16;           // float4s per filter row
    #pragma unroll 2
    for (int i = tid; i < 32 * KW4; i += T1) {
        const int r  = i / KW4;
        const int k4 = i - r * KW4;
        *reinterpret_cast<float4*>(fs + r * PITCH + 4 * k4) =
            __ldg(reinterpret_cast<const float4*>(filt + (f0 + r) * (W * 64)) + k4);
    }
}

// filters 96..99 as (f,l)-pairs across lanes: f = lane&3, l = pass*8 + lane>>2
template<int W>
__device__ __forceinline__ void tail_branch(const float* __restrict__ filt,
                                            const float* __restrict__ cv,
                                            int idx_lane, int lane,
                                            float* __restrict__ outrow)
{
    constexpr int L = 17 - W;
    const int f = 96 + (lane & 3);
    const float* frow = filt + f * (W * 64);
    float m = -2.0f;
    #pragma unroll
    for (int pass = 0; pass < 2; pass++) {
        const int l = pass * 8 + (lane >> 2);
        const bool act = (l < L);
        u64 a0 = 0ull, a1 = 0ull;
        #pragma unroll
        for (int c = 0; c < W; c++) {
            // idx of char (l+c), fetched from the lane that holds it
            const int id = __shfl_sync(0xffffffffu, idx_lane, (l + c) & 15);
            const float4* e  = reinterpret_cast<const float4*>(cv + id * 64);
            const float4* fr = reinterpret_cast<const float4*>(frow + c * 64);
            if (act) {
                #pragma unroll
                for (int q = 0; q < 16; q++) {
                    const float4 ev = __ldg(e + q);
                    const float4 fv = __ldg(fr + q);
                    ffma2(a0, pack2(ev.x, ev.y), pack2(fv.x, fv.y));
                    ffma2(a1, pack2(ev.z, ev.w), pack2(fv.z, fv.w));
                }
            }
        }
        if (act) m = fmaxf(m, tanh_fast(hadd2(a0) + hadd2(a1)));
    }
    #pragma unroll
    for (int s = 4; s < 32; s <<= 1)
        m = fmaxf(m, __shfl_xor_sync(0xffffffffu, m, s));
    if (lane < 4) outrow[96 + lane] = m;
}

template<int W>
__device__ __forceinline__ void run_branch(const float* __restrict__ filt,
                                           const float* __restrict__ cv,
                                           float* fs,
                                           const float4* const (&ep)[16],
                                           int idx_lane, int tid, int lane,
                                           float* __restrict__ outrow)
{
    #pragma unroll 1
    for (int t = 0; t < 3; t++) {
        __syncthreads();
        stage_filters<W>(filt, fs, 32 * t, tid);
        __syncthreads();
        outrow[32 * t + lane] = conv_dot<W>(ep, fs + lane * PITCH);
    }
    tail_branch<W>(filt, cv, idx_lane, lane, outrow);
}

__global__ void __launch_bounds__(T1, 2)
conv_kernel(const int*   __restrict__ idxs,
            const float* __restrict__ cv,
            const float* __restrict__ f2, const float* __restrict__ f3,
            const float* __restrict__ f4, const float* __restrict__ f5)
{
    extern __shared__ float fs[];

    const int tid   = threadIdx.x;
    const int warp  = tid >> 5;
    const int lane  = tid & 31;
    const int token = blockIdx.x * TPC + warp;

    const int* tip = idxs + token * 16;
    const int4 i0 = __ldg(reinterpret_cast<const int4*>(tip) + 0);
    const int4 i1 = __ldg(reinterpret_cast<const int4*>(tip) + 1);
    const int4 i2 = __ldg(reinterpret_cast<const int4*>(tip) + 2);
    const int4 i3 = __ldg(reinterpret_cast<const int4*>(tip) + 3);

    const float4* ep[16];
    ep[ 0] = reinterpret_cast<const float4*>(cv + i0.x * 64);
    ep[ 1] = reinterpret_cast<const float4*>(cv + i0.y * 64);
    ep[ 2] = reinterpret_cast<const float4*>(cv + i0.z * 64);
    ep[ 3] = reinterpret_cast<const float4*>(cv + i0.w * 64);
    ep[ 4] = reinterpret_cast<const float4*>(cv + i1.x * 64);
    ep[ 5] = reinterpret_cast<const float4*>(cv + i1.y * 64);
    ep[ 6] = reinterpret_cast<const float4*>(cv + i1.z * 64);
    ep[ 7] = reinterpret_cast<const float4*>(cv + i1.w * 64);
    ep[ 8] = reinterpret_cast<const float4*>(cv + i2.x * 64);
    ep[ 9] = reinterpret_cast<const float4*>(cv + i2.y * 64);
    ep[10] = reinterpret_cast<const float4*>(cv + i2.z * 64);
    ep[11] = reinterpret_cast<const float4*>(cv + i2.w * 64);
    ep[12] = reinterpret_cast<const float4*>(cv + i3.x * 64);
    ep[13] = reinterpret_cast<const float4*>(cv + i3.y * 64);
    ep[14] = reinterpret_cast<const float4*>(cv + i3.z * 64);
    ep[15] = reinterpret_cast<const float4*>(cv + i3.w * 64);

    const int idx_lane = __ldg(tip + (lane & 15));   // for tail shuffles

    float* outrow = g_outs + (size_t)token * 400;
    run_branch<2>(f2, cv, fs, ep, idx_lane, tid, lane, outrow + 0);
    run_branch<3>(f3, cv, fs, ep, idx_lane, tid, lane, outrow + 100);
    run_branch<4>(f4, cv, fs, ep, idx_lane, tid, lane, outrow + 200);
    run_branch<5>(f5, cv, fs, ep, idx_lane, tid, lane, outrow + 300);
}

// ---------------------------------------------------------------------------
// Kernel 2: projection (400->128, no bias) + 2 highway layers.
// 512 threads = 4 token-quads x 128 channels; 16 tokens/CTA, 4 per thread.
// Weights staged in smem k-chunks (coalesced LDG, padded pitch 44 -> odd quad
// stride, conflict-free LDS.128). x values broadcast from smem.
// ---------------------------------------------------------------------------
#define T2    512
#define TOK2  16
#define TPT   4
#define XP    132                         // s_x row pitch (floats)
#define WP    44                          // weight chunk row pitch (floats)
#define SMEM2_BYTES ((TOK2 * XP + 2 * 128 * WP) * 4)   // 53504 B

__device__ __forceinline__ void hwy_layer(const float* __restrict__ tw,
                                          const float* __restrict__ tb,
                                          const float* __restrict__ gw,
                                          const float* __restrict__ gb,
                                          float x[TPT],
                                          float* s_x, float* s_wa, float* s_wb,
                                          int tq, int n, int tid)
{
    u64 at[TPT], ag[TPT];
    #pragma unroll
    for (int i = 0; i < TPT; i++) { at[i] = 0ull; ag[i] = 0ull; }

    #pragma unroll 1
    for (int kc = 0; kc < 4; kc++) {
        const int k0 = kc * 32;
        __syncthreads();
        for (int i = tid; i < 128 * 8; i += T2) {     // 128 rows x 8 float4
            const int r = i >> 3, k4 = i & 7;
            *reinterpret_cast<float4*>(s_wa + r * WP + 4 * k4) =
                __ldg(reinterpret_cast<const float4*>(tw + r * 128 + k0) + k4);
            *reinterpret_cast<float4*>(s_wb + r * WP + 4 * k4) =
                __ldg(reinterpret_cast<const float4*>(gw + r * 128 + k0) + k4);
        }
        __syncthreads();
        #pragma unroll
        for (int k4 = 0; k4 < 8; k4++) {
            const ulonglong2 wt = *reinterpret_cast<const ulonglong2*>(s_wa + n * WP + 4 * k4);
            const ulonglong2 wg = *reinterpret_cast<const ulonglong2*>(s_wb + n * WP + 4 * k4);
            #pragma unroll
            for (int i = 0; i < TPT; i++) {
                const ulonglong2 xv = *reinterpret_cast<const ulonglong2*>(
                    s_x + (tq * TPT + i) * XP + k0 + 4 * k4);
                ffma2(at[i], xv.x, wt.x); ffma2(at[i], xv.y, wt.y);
                ffma2(ag[i], xv.x, wg.x); ffma2(ag[i], xv.y, wg.y);
            }
        }
    }
    const float tbv = __ldg(tb + n), gbv = __ldg(gb + n);
    __syncthreads();                       // all s_x reads done before overwrite
    #pragma unroll
    for (int i = 0; i < TPT; i++) {
        const float tv = fmaxf(hadd2(at[i]) + tbv, 0.0f);
        const float z  = hadd2(ag[i]) + gbv;
        const float g  = 0.5f * tanh_fast(0.5f * z) + 0.5f;   // sigmoid(z)
        x[i] = g * tv + (1.0f - g) * x[i];
        s_x[(tq * TPT + i) * XP + n] = x[i];
    }
    __syncthreads();
}

__global__ void __launch_bounds__(T2, 2)
head_kernel(const float* __restrict__ wp,
            const float* __restrict__ tw0, const float* __restrict__ tb0,
            const float* __restrict__ tw1, const float* __restrict__ tb1,
            const float* __restrict__ gw0, const float* __restrict__ gb0,
            const float* __restrict__ gw1, const float* __restrict__ gb1,
            float* __restrict__ out)
{
    extern __shared__ float smem2[];
    float* s_x  = smem2;                   // [16][132]
    float* s_wa = s_x + TOK2 * XP;         // [128][44]
    float* s_wb = s_wa + 128 * WP;         // [128][44]

    const int tid  = threadIdx.x;
    const int tq   = tid >> 7;             // 0..3
    const int n    = tid & 127;            // output channel
    const int tok0 = blockIdx.x * TOK2;

    // ---- projection: 10 chunks of 40 over k=400 --------------------------
    u64 acc[TPT];
    #pragma unroll
    for (int i = 0; i < TPT; i++) acc[i] = 0ull;

    #pragma unroll 1
    for (int kc = 0; kc < 10; kc++) {
        const int k0 = kc * 40;
        __syncthreads();
        for (int i = tid; i < 128 * 10; i += T2) {    // wp chunk
            const int r = i / 10, k4 = i - r * 10;
            *reinterpret_cast<float4*>(s_wa + r * WP + 4 * k4) =
                __ldg(reinterpret_cast<const float4*>(wp + r * 400 + k0) + k4);
        }
        if (tid < TOK2 * 10) {                        // conv-output chunk
            const int r = tid / 10, k4 = tid - r * 10;
            *reinterpret_cast<float4*>(s_wb + r * WP + 4 * k4) =
                *reinterpret_cast<const float4*>(g_outs + (size_t)(tok0 + r) * 400 + k0 + 4 * k4);
        }
        __syncthreads();
        #pragma unroll
        for (int k4 = 0; k4 < 10; k4++) {
            const ulonglong2 w = *reinterpret_cast<const ulonglong2*>(s_wa + n * WP + 4 * k4);
            #pragma unroll
            for (int i = 0; i < TPT; i++) {
                const ulonglong2 xv = *reinterpret_cast<const ulonglong2*>(
                    s_wb + (tq * TPT + i) * WP + 4 * k4);
                ffma2(acc[i], xv.x, w.x); ffma2(acc[i], xv.y, w.y);
            }
        }
    }
    float x[TPT];
    __syncthreads();
    #pragma unroll
    for (int i = 0; i < TPT; i++) {
        x[i] = hadd2(acc[i]);
        s_x[(tq * TPT + i) * XP + n] = x[i];
    }
    __syncthreads();

    // ---- 2 highway layers ------------------------------------------------
    hwy_layer(tw0, tb0, gw0, gb0, x, s_x, s_wa, s_wb, tq, n, tid);
    hwy_layer(tw1, tb1, gw1, gb1, x, s_x, s_wa, s_wb, tq, n, tid);

    #pragma unroll
    for (int i = 0; i < TPT; i++)
        out[(size_t)(tok0 + tq * TPT + i) * 128 + n] = x[i];
}

// ---------------------------------------------------------------------------
extern "C" void kernel_launch(void* const* d_in, const int* in_sizes, int n_in,
                              void* d_out, int out_size)
{
    const int*   idxs = (const int*)  d_in[0];
    const float* cv   = (const float*)d_in[1];
    const float* f2   = (const float*)d_in[2];
    const float* f3   = (const float*)d_in[3];
    const float* f4   = (const float*)d_in[4];
    const float* f5   = (const float*)d_in[5];
    const float* wp   = (const float*)d_in[6];
    const float* tw0  = (const float*)d_in[7];
    const float* tb0  = (const float*)d_in[8];
    const float* tw1  = (const float*)d_in[9];
    const float* tb1  = (const float*)d_in[10];
    const float* gw0  = (const float*)d_in[11];
    const float* gb0  = (const float*)d_in[12];
    const float* gw1  = (const float*)d_in[13];
    const float* gb1  = (const float*)d_in[14];
    float* out = (float*)d_out;

    static bool attr_done = false;
    if (!attr_done) {
        cudaFuncSetAttribute(conv_kernel,
                             cudaFuncAttributeMaxDynamicSharedMemorySize, SMEM1_BYTES);
        cudaFuncSetAttribute(head_kernel,
                             cudaFuncAttributeMaxDynamicSharedMemorySize, SMEM2_BYTES);
        attr_done = true;
    }

    conv_kernel<<<NTOK / TPC, T1, SMEM1_BYTES>>>(idxs, cv, f2, f3, f4, f5);
    head_kernel<<<NTOK / TOK2, T2, SMEM2_BYTES>>>(wp, tw0, tb0, tw1, tb1,
                                                  gw0, gb0, gw1, gb1, out);
}

// round 3
// speedup vs baseline: 1.4520x; 1.4520x over previous
#include <cuda_runtime.h>

// ---------------------------------------------------------------------------
// CharacterEmbeddingLayer: char-CNN (windows 2..5, 100 filters each, tanh +
// maxpool) -> 400 feats -> 400x128 projection -> 2 highway layers -> [.,128].
// ---------------------------------------------------------------------------

#define NTOK  25600      // 64*400 tokens
#define NF    100

typedef unsigned long long u64;

// scratch for conv outputs: [NTOK, 400] fp32
__device__ float g_outs[(size_t)NTOK * 400];

// ---------------- packed fp32x2 helpers (sm_100+) ---------------------------
__device__ __forceinline__ void ffma2(u64 &acc, u64 a, u64 b) {
    asm("fma.rn.f32x2 %0, %1, %2, %0;" : "+l"(acc) : "l"(a), "l"(b));
}
__device__ __forceinline__ float hadd2(u64 v) {
    float lo, hi;
    asm("mov.b64 {%0, %1}, %2;" : "=f"(lo), "=f"(hi) : "l"(v));
    return lo + hi;
}
__device__ __forceinline__ float tanh_fast(float x) {
    float y;
    asm("tanh.approx.f32 %0, %1;" : "=f"(y) : "f"(x));
    return y;
}

// ---------------------------------------------------------------------------
// Kernel 1: conv branches. 8 tokens/CTA (1 token per warp), 256 threads,
// 2 CTAs/SM (128-reg budget). Embeds live in smem (pitch 68 -> stride-4 bank
// pattern, conflict-free LDS.128; broadcast reads cost 1 wavefront).
// Filters staged in smem: 3 tiles of 32 (lane = filter) + filters 96..99
// staged into rows 32..35 and handled by a position-parallel tail.
// ---------------------------------------------------------------------------
#define TPC      8
#define T1       256
#define EPITCH   68                        // floats per embed row
#define FPITCH   324                       // floats per filter row (16B-aligned)
#define FROWS    36
#define ES_FLOATS (TPC * 16 * EPITCH)      // 8704
#define SMEM1_BYTES ((ES_FLOATS + FROWS * FPITCH) * 4 + TPC * 16 * 4)

template<int W>
__device__ __forceinline__ float conv_dot(const float* __restrict__ es_tok,
                                          const float* __restrict__ frow)
{
    constexpr int L = 17 - W;              // valid window positions
    u64 acc[L];
    #pragma unroll
    for (int l = 0; l < L; l++) acc[l] = 0ull;

    #pragma unroll 1
    for (int d4 = 0; d4 < 16; d4++) {      // 4 fp32 of the d-dim per step
        ulonglong2 fv[W];
        #pragma unroll
        for (int p = 0; p < W; p++)
            fv[p] = *reinterpret_cast<const ulonglong2*>(frow + p * 64 + 4 * d4);
        #pragma unroll
        for (int j = 0; j < 16; j++) {
            const ulonglong2 ev = *reinterpret_cast<const ulonglong2*>(
                es_tok + j * EPITCH + 4 * d4);          // warp-broadcast
            #pragma unroll
            for (int p = 0; p < W; p++) {
                const int l = j - p;                    // folded at compile time
                if (l >= 0 && l < L) {
                    ffma2(acc[l], ev.x, fv[p].x);
                    ffma2(acc[l], ev.y, fv[p].y);
                }
            }
        }
    }
    float vm = -2.0f;                       // tanh in [-1,1]
    #pragma unroll
    for (int l = 0; l < L; l++)
        vm = fmaxf(vm, tanh_fast(hadd2(acc[l])));
    return vm;
}

template<int W>
__device__ __forceinline__ void stage_filters(const float* __restrict__ filt,
                                              float* fs, int f0, int nr, int tid)
{
    const int KW4 = W * 16;                // float4s per filter row
    for (int i = tid; i < nr * KW4; i += T1) {
        const int r  = i / KW4;
        const int k4 = i - r * KW4;
        *reinterpret_cast<float4*>(fs + r * FPITCH + 4 * k4) =
            __ldg(reinterpret_cast<const float4*>(filt + (f0 + r) * (W * 64)) + k4);
    }
}

// filters 96..99 (staged in fs rows 32..35): lane = position l, each active
// lane accumulates all 4 filters; warp max-reduce per filter at the end.
template<int W>
__device__ __forceinline__ void tail_branch(const float* __restrict__ es_tok,
                                            const float* __restrict__ fs,
                                            int lane, float* __restrict__ outrow)
{
    constexpr int L = 17 - W;
    const bool act = (lane < L);
    const int  l   = act ? lane : 0;

    u64 a0[4], a1[4];
    #pragma unroll
    for (int f = 0; f < 4; f++) { a0[f] = 0ull; a1[f] = 0ull; }

    if (act) {
        #pragma unroll
        for (int c = 0; c < W; c++) {
            #pragma unroll 4
            for (int q = 0; q < 16; q++) {
                const ulonglong2 ev = *reinterpret_cast<const ulonglong2*>(
                    es_tok + (l + c) * EPITCH + 4 * q);
                #pragma unroll
                for (int f = 0; f < 4; f++) {
                    const ulonglong2 fv = *reinterpret_cast<const ulonglong2*>(
                        fs + (32 + f) * FPITCH + c * 64 + 4 * q);  // broadcast
                    ffma2(a0[f], ev.x, fv.x);
                    ffma2(a1[f], ev.y, fv.y);
                }
            }
        }
    }
    float m[4];
    #pragma unroll
    for (int f = 0; f < 4; f++)
        m[f] = act ? tanh_fast(hadd2(a0[f]) + hadd2(a1[f])) : -2.0f;
    #pragma unroll
    for (int f = 0; f < 4; f++)
        #pragma unroll
        for (int s = 1; s < 32; s <<= 1)
            m[f] = fmaxf(m[f], __shfl_xor_sync(0xffffffffu, m[f], s));
    if (lane < 4) outrow[96 + lane] = m[lane];
}

template<int W>
__device__ __forceinline__ void run_branch(const float* __restrict__ filt,
                                           const float* __restrict__ es_tok,
                                           float* fs, int tid, int lane,
                                           float* __restrict__ outrow)
{
    #pragma unroll 1
    for (int t = 0; t < 3; t++) {
        __syncthreads();                    // fs free to overwrite
        stage_filters<W>(filt, fs, 32 * t, (t == 2) ? 36 : 32, tid);
        __syncthreads();
        outrow[32 * t + lane] = conv_dot<W>(es_tok, fs + lane * FPITCH);
        if (t == 2) tail_branch<W>(es_tok, fs, lane, outrow);
    }
}

__global__ void __launch_bounds__(T1, 2)
conv_kernel(const int*   __restrict__ idxs,
            const float* __restrict__ cv,
            const float* __restrict__ f2, const float* __restrict__ f3,
            const float* __restrict__ f4, const float* __restrict__ f5)
{
    extern __shared__ char smem_raw[];
    float* es   = reinterpret_cast<float*>(smem_raw);
    float* fs   = es + ES_FLOATS;
    int*   sidx = reinterpret_cast<int*>(fs + FROWS * FPITCH);

    const int tid   = threadIdx.x;
    const int warp  = tid >> 5;
    const int lane  = tid & 31;
    const int tok0  = blockIdx.x * TPC;

    if (tid < TPC * 16)
        sidx[tid] = __ldg(idxs + tok0 * 16 + tid);
    __syncthreads();

    // gather embeds: es[(t*16+j)*EPITCH + d] = cv[idx][d]  (float4 granularity)
    for (int i = tid; i < TPC * 16 * 16; i += T1) {
        const int t = i >> 8, j = (i >> 4) & 15, q = i & 15;
        *reinterpret_cast<float4*>(es + (t * 16 + j) * EPITCH + 4 * q) =
            __ldg(reinterpret_cast<const float4*>(cv + sidx[t * 16 + j] * 64) + q);
    }
    // (leading __syncthreads inside run_branch orders the fill vs. compute)

    const float* es_tok = es + warp * 16 * EPITCH;
    float* outrow = g_outs + (size_t)(tok0 + warp) * 400;
    run_branch<2>(f2, es_tok, fs, tid, lane, outrow + 0);
    run_branch<3>(f3, es_tok, fs, tid, lane, outrow + 100);
    run_branch<4>(f4, es_tok, fs, tid, lane, outrow + 200);
    run_branch<5>(f5, es_tok, fs, tid, lane, outrow + 300);
}

// ---------------------------------------------------------------------------
// Kernel 2: projection (400->128) + 2 highway layers.
// 256 threads = 2 token-octets x 128 channels; 16 tokens/CTA, 8 per thread
// (TPT=8 balances smem crossbar vs fma: 16 wavefronts vs 16 fma-cycles/k4).
// ---------------------------------------------------------------------------
#define T2    256
#define TOK2  16
#define TPT   8
#define XP    132                          // s_x row pitch (floats)
#define WP    44                           // weight chunk row pitch (floats)
#define SMEM2_BYTES ((TOK2 * XP + 2 * 128 * WP) * 4)   // 53504 B

__device__ __forceinline__ void hwy_layer(const float* __restrict__ tw,
                                          const float* __restrict__ tb,
                                          const float* __restrict__ gw,
                                          const float* __restrict__ gb,
                                          float x[TPT],
                                          float* s_x, float* s_wa, float* s_wb,
                                          int tq, int n, int tid)
{
    u64 at[TPT], ag[TPT];
    #pragma unroll
    for (int i = 0; i < TPT; i++) { at[i] = 0ull; ag[i] = 0ull; }

    #pragma unroll 1
    for (int kc = 0; kc < 4; kc++) {
        const int k0 = kc * 32;
        __syncthreads();
        for (int i = tid; i < 128 * 8; i += T2) {      // 128 rows x 8 float4
            const int r = i >> 3, k4 = i & 7;
            *reinterpret_cast<float4*>(s_wa + r * WP + 4 * k4) =
                __ldg(reinterpret_cast<const float4*>(tw + r * 128 + k0) + k4);
            *reinterpret_cast<float4*>(s_wb + r * WP + 4 * k4) =
                __ldg(reinterpret_cast<const float4*>(gw + r * 128 + k0) + k4);
        }
        __syncthreads();
        #pragma unroll
        for (int k4 = 0; k4 < 8; k4++) {
            const ulonglong2 wt = *reinterpret_cast<const ulonglong2*>(s_wa + n * WP + 4 * k4);
            const ulonglong2 wg = *reinterpret_cast<const ulonglong2*>(s_wb + n * WP + 4 * k4);
            #pragma unroll
            for (int i = 0; i < TPT; i++) {
                const ulonglong2 xv = *reinterpret_cast<const ulonglong2*>(
                    s_x + (tq * TPT + i) * XP + k0 + 4 * k4);
                ffma2(at[i], xv.x, wt.x); ffma2(at[i], xv.y, wt.y);
                ffma2(ag[i], xv.x, wg.x); ffma2(ag[i], xv.y, wg.y);
            }
        }
    }
    const float tbv = __ldg(tb + n), gbv = __ldg(gb + n);
    __syncthreads();                        // all s_x reads done before overwrite
    #pragma unroll
    for (int i = 0; i < TPT; i++) {
        const float tv = fmaxf(hadd2(at[i]) + tbv, 0.0f);
        const float z  = hadd2(ag[i]) + gbv;
        const float g  = 0.5f * tanh_fast(0.5f * z) + 0.5f;   // sigmoid(z)
        x[i] = g * tv + (1.0f - g) * x[i];
        s_x[(tq * TPT + i) * XP + n] = x[i];
    }
    __syncthreads();
}

__global__ void __launch_bounds__(T2, 2)
head_kernel(const float* __restrict__ wp,
            const float* __restrict__ tw0, const float* __restrict__ tb0,
            const float* __restrict__ tw1, const float* __restrict__ tb1,
            const float* __restrict__ gw0, const float* __restrict__ gb0,
            const float* __restrict__ gw1, const float* __restrict__ gb1,
            float* __restrict__ out)
{
    extern __shared__ float smem2[];
    float* s_x  = smem2;                    // [16][132]
    float* s_wa = s_x + TOK2 * XP;          // [128][44]
    float* s_wb = s_wa + 128 * WP;          // [128][44] (also outs chunks)

    const int tid  = threadIdx.x;
    const int tq   = tid >> 7;              // 0..1
    const int n    = tid & 127;             // output channel
    const int tok0 = blockIdx.x * TOK2;

    // ---- projection: 10 chunks of 40 over k=400 --------------------------
    u64 acc[TPT];
    #pragma unroll
    for (int i = 0; i < TPT; i++) acc[i] = 0ull;

    #pragma unroll 1
    for (int kc = 0; kc < 10; kc++) {
        const int k0 = kc * 40;
        __syncthreads();
        for (int i = tid; i < 128 * 10; i += T2) {     // wp chunk
            const int r = i / 10, k4 = i - r * 10;
            *reinterpret_cast<float4*>(s_wa + r * WP + 4 * k4) =
                __ldg(reinterpret_cast<const float4*>(wp + r * 400 + k0) + k4);
        }
        if (tid < TOK2 * 10) {                         // conv-output chunk
            const int r = tid / 10, k4 = tid - r * 10;
            *reinterpret_cast<float4*>(s_wb + r * WP + 4 * k4) =
                *reinterpret_cast<const float4*>(g_outs + (size_t)(tok0 + r) * 400 + k0 + 4 * k4);
        }
        __syncthreads();
        #pragma unroll
        for (int k4 = 0; k4 < 10; k4++) {
            const ulonglong2 w = *reinterpret_cast<const ulonglong2*>(s_wa + n * WP + 4 * k4);
            #pragma unroll
            for (int i = 0; i < TPT; i++) {
                const ulonglong2 xv = *reinterpret_cast<const ulonglong2*>(
                    s_wb + (tq * TPT + i) * WP + 4 * k4);
                ffma2(acc[i], xv.x, w.x); ffma2(acc[i], xv.y, w.y);
            }
        }
    }
    float x[TPT];
    __syncthreads();
    #pragma unroll
    for (int i = 0; i < TPT; i++) {
        x[i] = hadd2(acc[i]);
        s_x[(tq * TPT + i) * XP + n] = x[i];
    }
    __syncthreads();

    // ---- 2 highway layers ------------------------------------------------
    hwy_layer(tw0, tb0, gw0, gb0, x, s_x, s_wa, s_wb, tq, n, tid);
    hwy_layer(tw1, tb1, gw1, gb1, x, s_x, s_wa, s_wb, tq, n, tid);

    #pragma unroll
    for (int i = 0; i < TPT; i++)
        out[(size_t)(tok0 + tq * TPT + i) * 128 + n] = x[i];
}

// ---------------------------------------------------------------------------
extern "C" void kernel_launch(void* const* d_in, const int* in_sizes, int n_in,
                              void* d_out, int out_size)
{
    const int*   idxs = (const int*)  d_in[0];
    const float* cv   = (const float*)d_in[1];
    const float* f2   = (const float*)d_in[2];
    const float* f3   = (const float*)d_in[3];
    const float* f4   = (const float*)d_in[4];
    const float* f5   = (const float*)d_in[5];
    const float* wp   = (const float*)d_in[6];
    const float* tw0  = (const float*)d_in[7];
    const float* tb0  = (const float*)d_in[8];
    const float* tw1  = (const float*)d_in[9];
    const float* tb1  = (const float*)d_in[10];
    const float* gw0  = (const float*)d_in[11];
    const float* gb0  = (const float*)d_in[12];
    const float* gw1  = (const float*)d_in[13];
    const float* gb1  = (const float*)d_in[14];
    float* out = (float*)d_out;

    static bool attr_done = false;
    if (!attr_done) {
        cudaFuncSetAttribute(conv_kernel,
                             cudaFuncAttributeMaxDynamicSharedMemorySize, SMEM1_BYTES);
        cudaFuncSetAttribute(head_kernel,
                             cudaFuncAttributeMaxDynamicSharedMemorySize, SMEM2_BYTES);
        attr_done = true;
    }

    conv_kernel<<<NTOK / TPC, T1, SMEM1_BYTES>>>(idxs, cv, f2, f3, f4, f5);
    head_kernel<<<NTOK / TOK2, T2, SMEM2_BYTES>>>(wp, tw0, tb0, tw1, tb1,
                                                  gw0, gb0, gw1, gb1, out);
}

// round 4
// speedup vs baseline: 5.6901x; 3.9187x over previous
#include <cuda_runtime.h>

// ---------------------------------------------------------------------------
// CharacterEmbeddingLayer via vocabulary factorization:
//   conv dot-products depend only on (char id, piece, filter) -> precompute
//   PP[char][piece][filter] once (96x14x100), then conv = table adds + max,
//   and tanh is monotonic so tanh moves outside the max.
// ---------------------------------------------------------------------------

#define NTOK  25600      // 64*400 tokens

typedef unsigned long long u64;

// PP table: [13 filter-chunks][96 chars][14 pieces][8 filters]  (~550 KB)
__device__ float g_pp[13 * 96 * 14 * 8];
// conv outputs: [NTOK][400]
__device__ float g_outs[(size_t)NTOK * 400];

// ---------------- packed fp32x2 helpers (sm_100+) ---------------------------
__device__ __forceinline__ void ffma2(u64 &acc, u64 a, u64 b) {
    asm("fma.rn.f32x2 %0, %1, %2, %0;" : "+l"(acc) : "l"(a), "l"(b));
}
__device__ __forceinline__ u64 fadd2(u64 a, u64 b) {
    u64 r; asm("add.rn.f32x2 %0, %1, %2;" : "=l"(r) : "l"(a), "l"(b)); return r;
}
__device__ __forceinline__ void unpack2(u64 v, float &lo, float &hi) {
    asm("mov.b64 {%0, %1}, %2;" : "=f"(lo), "=f"(hi) : "l"(v));
}
__device__ __forceinline__ float hadd2(u64 v) {
    float lo, hi; unpack2(v, lo, hi); return lo + hi;
}
__device__ __forceinline__ float tanh_fast(float x) {
    float y;
    asm("tanh.approx.f32 %0, %1;" : "=f"(y) : "f"(x));
    return y;
}

// ---------------------------------------------------------------------------
// Kernel A: precompute PP.  grid = 96 (char), 256 threads.
// PP[g][c][pg][j8] = dot(cv[c], filtW[f = g*8+j8][piece pl]),  f>=100 -> 0.
// Piece map: pg 0..1 -> filt2, 2..4 -> filt3, 5..8 -> filt4, 9..13 -> filt5.
// ---------------------------------------------------------------------------
__global__ void pp_kernel(const float* __restrict__ cv,
                          const float* __restrict__ f2, const float* __restrict__ f3,
                          const float* __restrict__ f4, const float* __restrict__ f5)
{
    __shared__ float scv[64];
    const int c = blockIdx.x;
    if (threadIdx.x < 64) scv[threadIdx.x] = __ldg(cv + c * 64 + threadIdx.x);
    __syncthreads();

    for (int e = threadIdx.x; e < 14 * 104; e += blockDim.x) {
        const int pg = e / 104, j = e - pg * 104;   // j = filter 0..103
        float s = 0.0f;
        if (j < 100) {
            const float* fp; int pl, RL;
            if (pg < 2)      { fp = f2; pl = pg;     RL = 2; }
            else if (pg < 5) { fp = f3; pl = pg - 2; RL = 3; }
            else if (pg < 9) { fp = f4; pl = pg - 5; RL = 4; }
            else             { fp = f5; pl = pg - 9; RL = 5; }
            const float4* fr = reinterpret_cast<const float4*>(fp + (j * RL + pl) * 64);
            #pragma unroll 4
            for (int q = 0; q < 16; q++) {
                const float4 fv = __ldg(fr + q);
                s += scv[4*q]   * fv.x + scv[4*q+1] * fv.y
                   + scv[4*q+2] * fv.z + scv[4*q+3] * fv.w;
            }
        }
        g_pp[(((j >> 3) * 96 + c) * 14 + pg) * 8 + (j & 7)] = s;
    }
}

// ---------------------------------------------------------------------------
// Kernel B: conv as table sums.  grid = 400 (64 tokens/CTA), 256 threads.
// thread = (token t = tid>>2, filter-pair j2 = tid&3).  13 chunks of 8 filters.
// smem: chunk slice as u64 pairs, row (c,p) = 5 u64 (4 data + 1 pad, 40B pitch).
// Per branch W at position l: sum_p PP[idx[l+p]][pb+p][pair] (fadd2),
// running max, ONE tanh per filter at the end (monotonicity).
// ---------------------------------------------------------------------------
#define TB1  256
#define SMEMB_BYTES (96 * 14 * 5 * 8)      // 53760 B of u64 rows

template<int W, int PB, int BOFF>
__device__ __forceinline__ void branch_sum(const u64* __restrict__ s_pp,
                                           const int (&bix)[16],
                                           float* __restrict__ orow,
                                           int g, int j2)
{
    constexpr int L = 17 - W;
    float m0 = -1e30f, m1 = -1e30f;
    #pragma unroll
    for (int l = 0; l < L; l++) {
        u64 a = s_pp[bix[l] + PB * 5];
        #pragma unroll
        for (int p = 1; p < W; p++)
            a = fadd2(a, s_pp[bix[l + p] + (PB + p) * 5]);
        float lo, hi; unpack2(a, lo, hi);
        m0 = fmaxf(m0, lo);
        m1 = fmaxf(m1, hi);
    }
    if (g < 12 || j2 < 2) {     // chunk 12 holds filters 96..103; only 96..99 real
        float2 r;
        r.x = tanh_fast(m0);
        r.y = tanh_fast(m1);
        *reinterpret_cast<float2*>(orow + BOFF + g * 8 + j2 * 2) = r;
    }
}

__global__ void __launch_bounds__(TB1, 3)
conv_sum_kernel(const int* __restrict__ idxs)
{
    extern __shared__ u64 s_pp[];
    const int tid = threadIdx.x;
    const int t   = tid >> 2;
    const int j2  = tid & 3;
    const int token = blockIdx.x * 64 + t;

    // per-thread base indices into s_pp (u64 units): idx*14*5 + j2
    int bix[16];
    {
        const int4* ip4 = reinterpret_cast<const int4*>(idxs + token * 16);
        const int4 A = __ldg(ip4 + 0), B = __ldg(ip4 + 1);
        const int4 C = __ldg(ip4 + 2), D = __ldg(ip4 + 3);
        bix[ 0] = A.x * 70 + j2; bix[ 1] = A.y * 70 + j2;
        bix[ 2] = A.z * 70 + j2; bix[ 3] = A.w * 70 + j2;
        bix[ 4] = B.x * 70 + j2; bix[ 5] = B.y * 70 + j2;
        bix[ 6] = B.z * 70 + j2; bix[ 7] = B.w * 70 + j2;
        bix[ 8] = C.x * 70 + j2; bix[ 9] = C.y * 70 + j2;
        bix[10] = C.z * 70 + j2; bix[11] = C.w * 70 + j2;
        bix[12] = D.x * 70 + j2; bix[13] = D.y * 70 + j2;
        bix[14] = D.z * 70 + j2; bix[15] = D.w * 70 + j2;
    }

    float* orow = g_outs + (size_t)token * 400;

    #pragma unroll 1
    for (int g = 0; g < 13; g++) {
        __syncthreads();
        // stage chunk slice: 96*14*8 floats = 2688 float4, into padded u64 rows
        const float4* src = reinterpret_cast<const float4*>(g_pp + g * 10752);
        #pragma unroll 1
        for (int i = tid; i < 2688; i += TB1) {
            const float4 v = __ldg(src + i);
            const u64* pv = reinterpret_cast<const u64*>(&v);
            u64* d = s_pp + (i >> 1) * 5 + (i & 1) * 2;
            d[0] = pv[0];
            d[1] = pv[1];
        }
        __syncthreads();

        branch_sum<2, 0,   0>(s_pp, bix, orow, g, j2);
        branch_sum<3, 2, 100>(s_pp, bix, orow, g, j2);
        branch_sum<4, 5, 200>(s_pp, bix, orow, g, j2);
        branch_sum<5, 9, 300>(s_pp, bix, orow, g, j2);
    }
}

// ---------------------------------------------------------------------------
// Kernel 2 (unchanged from R3): projection (400->128) + 2 highway layers.
// 256 threads = 2 token-octets x 128 channels; 16 tokens/CTA, 8 per thread.
// ---------------------------------------------------------------------------
#define T2    256
#define TOK2  16
#define TPT   8
#define XP    132
#define WP    44
#define SMEM2_BYTES ((TOK2 * XP + 2 * 128 * WP) * 4)   // 53504 B

__device__ __forceinline__ void hwy_layer(const float* __restrict__ tw,
                                          const float* __restrict__ tb,
                                          const float* __restrict__ gw,
                                          const float* __restrict__ gb,
                                          float x[TPT],
                                          float* s_x, float* s_wa, float* s_wb,
                                          int tq, int n, int tid)
{
    u64 at[TPT], ag[TPT];
    #pragma unroll
    for (int i = 0; i < TPT; i++) { at[i] = 0ull; ag[i] = 0ull; }

    #pragma unroll 1
    for (int kc = 0; kc < 4; kc++) {
        const int k0 = kc * 32;
        __syncthreads();
        for (int i = tid; i < 128 * 8; i += T2) {
            const int r = i >> 3, k4 = i & 7;
            *reinterpret_cast<float4*>(s_wa + r * WP + 4 * k4) =
                __ldg(reinterpret_cast<const float4*>(tw + r * 128 + k0) + k4);
            *reinterpret_cast<float4*>(s_wb + r * WP + 4 * k4) =
                __ldg(reinterpret_cast<const float4*>(gw + r * 128 + k0) + k4);
        }
        __syncthreads();
        #pragma unroll
        for (int k4 = 0; k4 < 8; k4++) {
            const ulonglong2 wt = *reinterpret_cast<const ulonglong2*>(s_wa + n * WP + 4 * k4);
            const ulonglong2 wg = *reinterpret_cast<const ulonglong2*>(s_wb + n * WP + 4 * k4);
            #pragma unroll
            for (int i = 0; i < TPT; i++) {
                const ulonglong2 xv = *reinterpret_cast<const ulonglong2*>(
                    s_x + (tq * TPT + i) * XP + k0 + 4 * k4);
                ffma2(at[i], xv.x, wt.x); ffma2(at[i], xv.y, wt.y);
                ffma2(ag[i], xv.x, wg.x); ffma2(ag[i], xv.y, wg.y);
            }
        }
    }
    const float tbv = __ldg(tb + n), gbv = __ldg(gb + n);
    __syncthreads();
    #pragma unroll
    for (int i = 0; i < TPT; i++) {
        const float tv = fmaxf(hadd2(at[i]) + tbv, 0.0f);
        const float z  = hadd2(ag[i]) + gbv;
        const float g  = 0.5f * tanh_fast(0.5f * z) + 0.5f;   // sigmoid(z)
        x[i] = g * tv + (1.0f - g) * x[i];
        s_x[(tq * TPT + i) * XP + n] = x[i];
    }
    __syncthreads();
}

__global__ void __launch_bounds__(T2, 2)
head_kernel(const float* __restrict__ wp,
            const float* __restrict__ tw0, const float* __restrict__ tb0,
            const float* __restrict__ tw1, const float* __restrict__ tb1,
            const float* __restrict__ gw0, const float* __restrict__ gb0,
            const float* __restrict__ gw1, const float* __restrict__ gb1,
            float* __restrict__ out)
{
    extern __shared__ float smem2[];
    float* s_x  = smem2;                    // [16][132]
    float* s_wa = s_x + TOK2 * XP;          // [128][44]
    float* s_wb = s_wa + 128 * WP;          // [128][44]

    const int tid  = threadIdx.x;
    const int tq   = tid >> 7;
    const int n    = tid & 127;
    const int tok0 = blockIdx.x * TOK2;

    u64 acc[TPT];
    #pragma unroll
    for (int i = 0; i < TPT; i++) acc[i] = 0ull;

    #pragma unroll 1
    for (int kc = 0; kc < 10; kc++) {
        const int k0 = kc * 40;
        __syncthreads();
        for (int i = tid; i < 128 * 10; i += T2) {
            const int r = i / 10, k4 = i - r * 10;
            *reinterpret_cast<float4*>(s_wa + r * WP + 4 * k4) =
                __ldg(reinterpret_cast<const float4*>(wp + r * 400 + k0) + k4);
        }
        if (tid < TOK2 * 10) {
            const int r = tid / 10, k4 = tid - r * 10;
            *reinterpret_cast<float4*>(s_wb + r * WP + 4 * k4) =
                *reinterpret_cast<const float4*>(g_outs + (size_t)(tok0 + r) * 400 + k0 + 4 * k4);
        }
        __syncthreads();
        #pragma unroll
        for (int k4 = 0; k4 < 10; k4++) {
            const ulonglong2 w = *reinterpret_cast<const ulonglong2*>(s_wa + n * WP + 4 * k4);
            #pragma unroll
            for (int i = 0; i < TPT; i++) {
                const ulonglong2 xv = *reinterpret_cast<const ulonglong2*>(
                    s_wb + (tq * TPT + i) * WP + 4 * k4);
                ffma2(acc[i], xv.x, w.x); ffma2(acc[i], xv.y, w.y);
            }
        }
    }
    float x[TPT];
    __syncthreads();
    #pragma unroll
    for (int i = 0; i < TPT; i++) {
        x[i] = hadd2(acc[i]);
        s_x[(tq * TPT + i) * XP + n] = x[i];
    }
    __syncthreads();

    hwy_layer(tw0, tb0, gw0, gb0, x, s_x, s_wa, s_wb, tq, n, tid);
    hwy_layer(tw1, tb1, gw1, gb1, x, s_x, s_wa, s_wb, tq, n, tid);

    #pragma unroll
    for (int i = 0; i < TPT; i++)
        out[(size_t)(tok0 + tq * TPT + i) * 128 + n] = x[i];
}

// ---------------------------------------------------------------------------
extern "C" void kernel_launch(void* const* d_in, const int* in_sizes, int n_in,
                              void* d_out, int out_size)
{
    const int*   idxs = (const int*)  d_in[0];
    const float* cv   = (const float*)d_in[1];
    const float* f2   = (const float*)d_in[2];
    const float* f3   = (const float*)d_in[3];
    const float* f4   = (const float*)d_in[4];
    const float* f5   = (const float*)d_in[5];
    const float* wp   = (const float*)d_in[6];
    const float* tw0  = (const float*)d_in[7];
    const float* tb0  = (const float*)d_in[8];
    const float* tw1  = (const float*)d_in[9];
    const float* tb1  = (const float*)d_in[10];
    const float* gw0  = (const float*)d_in[11];
    const float* gb0  = (const float*)d_in[12];
    const float* gw1  = (const float*)d_in[13];
    const float* gb1  = (const float*)d_in[14];
    float* out = (float*)d_out;

    static bool attr_done = false;
    if (!attr_done) {
        cudaFuncSetAttribute(conv_sum_kernel,
                             cudaFuncAttributeMaxDynamicSharedMemorySize, SMEMB_BYTES);
        cudaFuncSetAttribute(head_kernel,
                             cudaFuncAttributeMaxDynamicSharedMemorySize, SMEM2_BYTES);
        attr_done = true;
    }

    pp_kernel<<<96, 256>>>(cv, f2, f3, f4, f5);
    conv_sum_kernel<<<NTOK / 64, TB1, SMEMB_BYTES>>>(idxs);
    head_kernel<<<NTOK / TOK2, T2, SMEM2_BYTES>>>(wp, tw0, tb0, tw1, tb1,
                                                  gw0, gb0, gw1, gb1, out);
}

// round 5
// speedup vs baseline: 6.4335x; 1.1306x over previous
#include <cuda_runtime.h>
#include <cstdint>

// ---------------------------------------------------------------------------
// CharacterEmbeddingLayer via vocabulary factorization:
//   conv dot-products depend only on (char id, piece, filter) -> precompute
//   PP[char][piece][filter] once (96x14x100), then conv = table adds + max,
//   and tanh is monotonic so tanh moves outside the max.
// Round 5: cp.async double-buffered staging everywhere; head reworked to
//   2 channels/thread (crossbar:fma <= 1) with 32 tokens/CTA.
// ---------------------------------------------------------------------------

#define NTOK  25600      // 64*400 tokens

typedef unsigned long long u64;

// PP table: [13 filter-chunks][96 chars][14 pieces][8 filters]
__device__ float g_pp[13 * 96 * 14 * 8];
// conv outputs: [NTOK][400]
__device__ float g_outs[(size_t)NTOK * 400];

// ---------------- packed fp32x2 + async helpers -----------------------------
__device__ __forceinline__ void ffma2(u64 &acc, u64 a, u64 b) {
    asm("fma.rn.f32x2 %0, %1, %2, %0;" : "+l"(acc) : "l"(a), "l"(b));
}
__device__ __forceinline__ u64 fadd2(u64 a, u64 b) {
    u64 r; asm("add.rn.f32x2 %0, %1, %2;" : "=l"(r) : "l"(a), "l"(b)); return r;
}
__device__ __forceinline__ void unpack2(u64 v, float &lo, float &hi) {
    asm("mov.b64 {%0, %1}, %2;" : "=f"(lo), "=f"(hi) : "l"(v));
}
__device__ __forceinline__ float hadd2(u64 v) {
    float lo, hi; unpack2(v, lo, hi); return lo + hi;
}
__device__ __forceinline__ float tanh_fast(float x) {
    float y;
    asm("tanh.approx.f32 %0, %1;" : "=f"(y) : "f"(x));
    return y;
}
__device__ __forceinline__ uint32_t smem_u32(const void* p) {
    return (uint32_t)__cvta_generic_to_shared(p);
}
__device__ __forceinline__ void cp16(uint32_t dst, const void* src) {
    asm volatile("cp.async.ca.shared.global [%0], [%1], 16;" :: "r"(dst), "l"(src));
}
__device__ __forceinline__ void cp8(uint32_t dst, const void* src) {
    asm volatile("cp.async.ca.shared.global [%0], [%1], 8;" :: "r"(dst), "l"(src));
}
__device__ __forceinline__ void cp_commit() {
    asm volatile("cp.async.commit_group;");
}
template<int N> __device__ __forceinline__ void cp_wait() {
    asm volatile("cp.async.wait_group %0;" :: "n"(N));
}

// ---------------------------------------------------------------------------
// Kernel A: precompute PP.  grid = (96 chars, 14 pieces), 128 threads.
// ---------------------------------------------------------------------------
__global__ void pp_kernel(const float* __restrict__ cv,
                          const float* __restrict__ f2, const float* __restrict__ f3,
                          const float* __restrict__ f4, const float* __restrict__ f5)
{
    __shared__ float scv[64];
    const int c  = blockIdx.x;
    const int pg = blockIdx.y;
    const int j  = threadIdx.x;
    if (j < 64) scv[j] = __ldg(cv + c * 64 + j);
    __syncthreads();

    if (j < 104) {
        float s = 0.0f;
        if (j < 100) {
            const float* fp; int pl, RL;
            if (pg < 2)      { fp = f2; pl = pg;     RL = 2; }
            else if (pg < 5) { fp = f3; pl = pg - 2; RL = 3; }
            else if (pg < 9) { fp = f4; pl = pg - 5; RL = 4; }
            else             { fp = f5; pl = pg - 9; RL = 5; }
            const float4* fr = reinterpret_cast<const float4*>(fp + (j * RL + pl) * 64);
            #pragma unroll 4
            for (int q = 0; q < 16; q++) {
                const float4 fv = __ldg(fr + q);
                s += scv[4*q]   * fv.x + scv[4*q+1] * fv.y
                   + scv[4*q+2] * fv.z + scv[4*q+3] * fv.w;
            }
        }
        g_pp[(((j >> 3) * 96 + c) * 14 + pg) * 8 + (j & 7)] = s;
    }
}

// ---------------------------------------------------------------------------
// Kernel B: conv as table sums.  grid = 400 (64 tokens/CTA), 256 threads.
// thread = (token t = tid>>2, filter-pair j2 = tid&3).  13 chunks of 8 filters,
// cp.async double-buffered. smem rows (c,pg) = 5 u64 (4 data + 1 pad, 40B).
// ---------------------------------------------------------------------------
#define TB1  256
#define CHUNK_U64 (96 * 14 * 5)            // 6720 u64 per buffer
#define SMEMB_BYTES (2 * CHUNK_U64 * 8)    // 107520 B

__device__ __forceinline__ void stage_chunk(uint32_t sbuf,
                                            const float* __restrict__ src, int tid)
{
    #pragma unroll 1
    for (int i = tid; i < 5376; i += TB1) {       // 1344 rows x 4 u64
        const int r = i >> 2, e = i & 3;
        cp8(sbuf + (uint32_t)(r * 5 + e) * 8u, src + 2 * i);
    }
}

template<int W, int PB, int BOFF>
__device__ __forceinline__ void branch_sum(const u64* __restrict__ s_pp,
                                           const int (&bix)[16],
                                           float* __restrict__ orow,
                                           int g, int j2)
{
    constexpr int L = 17 - W;
    float m0 = -1e30f, m1 = -1e30f;
    #pragma unroll
    for (int l = 0; l < L; l++) {
        u64 a = s_pp[bix[l] + PB * 5];
        #pragma unroll
        for (int p = 1; p < W; p++)
            a = fadd2(a, s_pp[bix[l + p] + (PB + p) * 5]);
        float lo, hi; unpack2(a, lo, hi);
        m0 = fmaxf(m0, lo);
        m1 = fmaxf(m1, hi);
    }
    if (g < 12 || j2 < 2) {     // chunk 12: only filters 96..99 are real
        float2 r;
        r.x = tanh_fast(m0);
        r.y = tanh_fast(m1);
        *reinterpret_cast<float2*>(orow + BOFF + g * 8 + j2 * 2) = r;
    }
}

__global__ void __launch_bounds__(TB1, 2)
conv_sum_kernel(const int* __restrict__ idxs)
{
    extern __shared__ u64 s_pp2[];
    u64* buf0 = s_pp2;
    u64* buf1 = s_pp2 + CHUNK_U64;
    const uint32_t sb0 = smem_u32(buf0);
    const uint32_t sb1 = smem_u32(buf1);

    const int tid = threadIdx.x;
    const int j2  = tid & 3;
    const int token = blockIdx.x * 64 + (tid >> 2);

    int bix[16];
    {
        const int4* ip4 = reinterpret_cast<const int4*>(idxs + token * 16);
        const int4 A = __ldg(ip4 + 0), B = __ldg(ip4 + 1);
        const int4 C = __ldg(ip4 + 2), D = __ldg(ip4 + 3);
        bix[ 0] = A.x * 70 + j2; bix[ 1] = A.y * 70 + j2;
        bix[ 2] = A.z * 70 + j2; bix[ 3] = A.w * 70 + j2;
        bix[ 4] = B.x * 70 + j2; bix[ 5] = B.y * 70 + j2;
        bix[ 6] = B.z * 70 + j2; bix[ 7] = B.w * 70 + j2;
        bix[ 8] = C.x * 70 + j2; bix[ 9] = C.y * 70 + j2;
        bix[10] = C.z * 70 + j2; bix[11] = C.w * 70 + j2;
        bix[12] = D.x * 70 + j2; bix[13] = D.y * 70 + j2;
        bix[14] = D.z * 70 + j2; bix[15] = D.w * 70 + j2;
    }

    float* orow = g_outs + (size_t)token * 400;

    stage_chunk(sb0, g_pp, tid);
    cp_commit();

    #pragma unroll 1
    for (int g = 0; g < 13; g++) {
        if (g < 12) {
            stage_chunk((g & 1) ? sb0 : sb1, g_pp + (g + 1) * 10752, tid);
            cp_commit();
            cp_wait<1>();
        } else {
            cp_wait<0>();
        }
        __syncthreads();
        const u64* sp = (g & 1) ? buf1 : buf0;
        branch_sum<2, 0,   0>(sp, bix, orow, g, j2);
        branch_sum<3, 2, 100>(sp, bix, orow, g, j2);
        branch_sum<4, 5, 200>(sp, bix, orow, g, j2);
        branch_sum<5, 9, 300>(sp, bix, orow, g, j2);
        __syncthreads();                  // buffer g&1 free for restage
    }
}

// ---------------------------------------------------------------------------
// Kernel C: head.  256 threads: c2 = tid&63 -> channels (c2, c2+64),
// tq = tid>>6 -> 8-token group; 32 tokens/CTA, grid 800.
// cp.async double-buffered weight staging; x broadcasts feed 2-4 acc sets.
// ---------------------------------------------------------------------------
#define T2    256
#define TOK2  32
#define XP    132                          // s_x row pitch (floats)
#define WP    44                           // staged row pitch (floats), 176B
#define WBUF  (256 * WP)                   // floats per buffer (11264)
#define SMEM2_BYTES ((TOK2 * XP + 2 * WBUF) * 4)   // 107008 B

__global__ void __launch_bounds__(T2, 2)
head_kernel(const float* __restrict__ wp,
            const float* __restrict__ tw0, const float* __restrict__ tb0,
            const float* __restrict__ tw1, const float* __restrict__ tb1,
            const float* __restrict__ gw0, const float* __restrict__ gb0,
            const float* __restrict__ gw1, const float* __restrict__ gb1,
            float* __restrict__ out)
{
    extern __shared__ float sm2[];
    float* s_x = sm2;                      // [32][132]
    float* w0  = s_x + TOK2 * XP;          // buffer 0: [256][44]
    float* w1  = w0 + WBUF;                // buffer 1
    const uint32_t wb[2] = { smem_u32(w0), smem_u32(w1) };
    float* const wf[2] = { w0, w1 };

    const int tid  = threadIdx.x;
    const int c2   = tid & 63;             // channels c2 and c2+64
    const int tq   = tid >> 6;             // token group 0..3
    const int tok0 = blockIdx.x * TOK2;

    // ---- projection: 10 chunks of 40 over k=400 --------------------------
    // staged layout: rows 0..127 = wp rows (chunk cols), rows 128..159 = outs.
    auto stage_proj = [&](int kc, uint32_t b) {
        #pragma unroll 1
        for (int i = tid; i < 1280; i += T2) {         // 128 rows x 10 quads
            const int r = i / 10, q = i - r * 10;
            cp16(b + (uint32_t)(r * WP + 4 * q) * 4u,
                 wp + r * 400 + kc * 40 + 4 * q);
        }
        #pragma unroll 1
        for (int i = tid; i < 320; i += T2) {          // 32 rows x 10 quads
            const int r = i / 10, q = i - r * 10;
            cp16(b + (uint32_t)((128 + r) * WP + 4 * q) * 4u,
                 g_outs + (size_t)(tok0 + r) * 400 + kc * 40 + 4 * q);
        }
    };

    u64 a0[8], a1[8];
    #pragma unroll
    for (int i = 0; i < 8; i++) { a0[i] = 0ull; a1[i] = 0ull; }

    stage_proj(0, wb[0]);
    cp_commit();
    #pragma unroll 1
    for (int kc = 0; kc < 10; kc++) {
        if (kc < 9) { stage_proj(kc + 1, wb[(kc + 1) & 1]); cp_commit(); cp_wait<1>(); }
        else        { cp_wait<0>(); }
        __syncthreads();
        const float* b  = wf[kc & 1];
        const float* wA = b + c2 * WP;
        const float* wB = b + (c2 + 64) * WP;
        const float* xb = b + 128 * WP + (tq * 8) * WP;
        #pragma unroll
        for (int k4 = 0; k4 < 10; k4++) {
            const ulonglong2 wa = *reinterpret_cast<const ulonglong2*>(wA + 4 * k4);
            const ulonglong2 wv = *reinterpret_cast<const ulonglong2*>(wB + 4 * k4);
            #pragma unroll
            for (int i = 0; i < 8; i++) {
                const ulonglong2 xv = *reinterpret_cast<const ulonglong2*>(xb + i * WP + 4 * k4);
                ffma2(a0[i], xv.x, wa.x); ffma2(a0[i], xv.y, wa.y);
                ffma2(a1[i], xv.x, wv.x); ffma2(a1[i], xv.y, wv.y);
            }
        }
        __syncthreads();
    }

    float x0[8], x1[8];
    #pragma unroll
    for (int i = 0; i < 8; i++) {
        x0[i] = hadd2(a0[i]);  s_x[(tq * 8 + i) * XP + c2]      = x0[i];
        x1[i] = hadd2(a1[i]);  s_x[(tq * 8 + i) * XP + c2 + 64] = x1[i];
    }
    __syncthreads();

    // ---- 2 highway layers: 4 chunks of 32 over k=128 ---------------------
    const float* TW[2] = { tw0, tw1 };
    const float* TBv[2] = { tb0, tb1 };
    const float* GW[2] = { gw0, gw1 };
    const float* GBv[2] = { gb0, gb1 };

    #pragma unroll 1
    for (int layer = 0; layer < 2; layer++) {
        const float* tw = TW[layer];
        const float* gw = GW[layer];
        // staged layout: rows 0..127 = tw, rows 128..255 = gw.
        auto stage_hwy = [&](int kc, uint32_t b) {
            #pragma unroll 1
            for (int i = tid; i < 2048; i += T2) {     // 256 rows x 8 quads
                const int r = i >> 3, q = i & 7;
                const float* src = (r < 128)
                    ? tw + r * 128 + kc * 32 + 4 * q
                    : gw + (r - 128) * 128 + kc * 32 + 4 * q;
                cp16(b + (uint32_t)(r * WP + 4 * q) * 4u, src);
            }
        };

        u64 at0[8], at1[8], ag0[8], ag1[8];
        #pragma unroll
        for (int i = 0; i < 8; i++) { at0[i] = at1[i] = ag0[i] = ag1[i] = 0ull; }

        stage_hwy(0, wb[0]);
        cp_commit();
        #pragma unroll 1
        for (int kc = 0; kc < 4; kc++) {
            if (kc < 3) { stage_hwy(kc + 1, wb[(kc + 1) & 1]); cp_commit(); cp_wait<1>(); }
            else        { cp_wait<0>(); }
            __syncthreads();
            const float* b = wf[kc & 1];
            #pragma unroll
            for (int k4 = 0; k4 < 8; k4++) {
                const ulonglong2 wt0 = *reinterpret_cast<const ulonglong2*>(b + c2 * WP + 4 * k4);
                const ulonglong2 wt1 = *reinterpret_cast<const ulonglong2*>(b + (c2 + 64) * WP + 4 * k4);
                const ulonglong2 wg0 = *reinterpret_cast<const ulonglong2*>(b + (128 + c2) * WP + 4 * k4);
                const ulonglong2 wg1 = *reinterpret_cast<const ulonglong2*>(b + (192 + c2) * WP + 4 * k4);
                #pragma unroll
                for (int i = 0; i < 8; i++) {
                    const ulonglong2 xv = *reinterpret_cast<const ulonglong2*>(
                        s_x + (tq * 8 + i) * XP + kc * 32 + 4 * k4);
                    ffma2(at0[i], xv.x, wt0.x); ffma2(at0[i], xv.y, wt0.y);
                    ffma2(at1[i], xv.x, wt1.x); ffma2(at1[i], xv.y, wt1.y);
                    ffma2(ag0[i], xv.x, wg0.x); ffma2(ag0[i], xv.y, wg0.y);
                    ffma2(ag1[i], xv.x, wg1.x); ffma2(ag1[i], xv.y, wg1.y);
                }
            }
            __syncthreads();              // buffer kc&1 free for restage
        }

        const float tb0v = __ldg(TBv[layer] + c2);
        const float tb1v = __ldg(TBv[layer] + c2 + 64);
        const float gb0v = __ldg(GBv[layer] + c2);
        const float gb1v = __ldg(GBv[layer] + c2 + 64);
        #pragma unroll
        for (int i = 0; i < 8; i++) {
            const float tv0 = fmaxf(hadd2(at0[i]) + tb0v, 0.0f);
            const float tv1 = fmaxf(hadd2(at1[i]) + tb1v, 0.0f);
            const float g0  = 0.5f * tanh_fast(0.5f * (hadd2(ag0[i]) + gb0v)) + 0.5f;
            const float g1  = 0.5f * tanh_fast(0.5f * (hadd2(ag1[i]) + gb1v)) + 0.5f;
            x0[i] = g0 * tv0 + (1.0f - g0) * x0[i];
            x1[i] = g1 * tv1 + (1.0f - g1) * x1[i];
            s_x[(tq * 8 + i) * XP + c2]      = x0[i];
            s_x[(tq * 8 + i) * XP + c2 + 64] = x1[i];
        }
        __syncthreads();
    }

    #pragma unroll
    for (int i = 0; i < 8; i++) {
        out[(size_t)(tok0 + tq * 8 + i) * 128 + c2]      = x0[i];
        out[(size_t)(tok0 + tq * 8 + i) * 128 + c2 + 64] = x1[i];
    }
}

// ---------------------------------------------------------------------------
extern "C" void kernel_launch(void* const* d_in, const int* in_sizes, int n_in,
                              void* d_out, int out_size)
{
    const int*   idxs = (const int*)  d_in[0];
    const float* cv   = (const float*)d_in[1];
    const float* f2   = (const float*)d_in[2];
    const float* f3   = (const float*)d_in[3];
    const float* f4   = (const float*)d_in[4];
    const float* f5   = (const float*)d_in[5];
    const float* wp   = (const float*)d_in[6];
    const float* tw0  = (const float*)d_in[7];
    const float* tb0  = (const float*)d_in[8];
    const float* tw1  = (const float*)d_in[9];
    const float* tb1  = (const float*)d_in[10];
    const float* gw0  = (const float*)d_in[11];
    const float* gb0  = (const float*)d_in[12];
    const float* gw1  = (const float*)d_in[13];
    const float* gb1  = (const float*)d_in[14];
    float* out = (float*)d_out;

    static bool attr_done = false;
    if (!attr_done) {
        cudaFuncSetAttribute(conv_sum_kernel,
                             cudaFuncAttributeMaxDynamicSharedMemorySize, SMEMB_BYTES);
        cudaFuncSetAttribute(head_kernel,
                             cudaFuncAttributeMaxDynamicSharedMemorySize, SMEM2_BYTES);
        attr_done = true;
    }

    pp_kernel<<<dim3(96, 14), 128>>>(cv, f2, f3, f4, f5);
    conv_sum_kernel<<<NTOK / 64, TB1, SMEMB_BYTES>>>(idxs);
    head_kernel<<<NTOK / TOK2, T2, SMEM2_BYTES>>>(wp, tw0, tb0, tw1, tb1,
                                                  gw0, gb0, gw1, gb1, out);
}